// round 1
// baseline (speedup 1.0000x reference)
#include <cuda_runtime.h>

#define BATCH 8
#define NBOX 1024
#define NCLS 32
#define MAXOUT 300
#define SCORE_THRF 0.5f
#define IOU_THRF 0.5f

// Scratch (no allocation allowed): per-class sorted keys + per-class kept candidates
__device__ unsigned long long g_skey[BATCH * NCLS * NBOX];   // 2 MB
__device__ unsigned long long g_cand[BATCH * NCLS * MAXOUT]; // 600 KB

__device__ __forceinline__ float decode_score(unsigned int hi) {
    unsigned int ordered = ~hi;
    if (ordered & 0x80000000u) return __uint_as_float(ordered & 0x7FFFFFFFu);
    return __uint_as_float(~ordered);
}

// ---------------------------------------------------------------------------
// Kernel 1: per-(batch,class) stable score-descending sort (bitonic, smem)
// key = (~ordered(score) << 32) | orig_index   -> ascending sort
// ---------------------------------------------------------------------------
__global__ void sort_kernel(const float* __restrict__ scores) {
    __shared__ unsigned long long s[NBOX];
    int b = blockIdx.x >> 5, c = blockIdx.x & 31;
    const float* sp = scores + ((size_t)b * NBOX) * NCLS + c;

    for (int n = threadIdx.x; n < NBOX; n += blockDim.x) {
        float v = sp[(size_t)n * NCLS];
        unsigned int bits = (v > SCORE_THRF) ? __float_as_uint(v) : 0xFF800000u; // -inf if invalid
        unsigned int ordered = (bits & 0x80000000u) ? ~bits : (bits | 0x80000000u);
        s[n] = ((unsigned long long)(~ordered) << 32) | (unsigned int)n;
    }
    for (int k = 2; k <= NBOX; k <<= 1) {
        for (int j = k >> 1; j > 0; j >>= 1) {
            __syncthreads();
            for (int i = threadIdx.x; i < NBOX; i += blockDim.x) {
                int ixj = i ^ j;
                if (ixj > i) {
                    unsigned long long a = s[i], bb = s[ixj];
                    bool up = ((i & k) == 0);
                    if ((a > bb) == up) { s[i] = bb; s[ixj] = a; }
                }
            }
        }
    }
    __syncthreads();
    unsigned long long* out = g_skey + ((size_t)b * NCLS + c) * NBOX;
    for (int i = threadIdx.x; i < NBOX; i += blockDim.x) out[i] = s[i];
}

// ---------------------------------------------------------------------------
// Kernel 2: per-(batch,class) greedy NMS + compaction of kept entries (<=300)
// ---------------------------------------------------------------------------
__global__ void nms_kernel(const float* __restrict__ boxes) {
    __shared__ float4 sbox[NBOX];
    __shared__ float sarea[NBOX];
    __shared__ int skeep[NBOX];
    __shared__ int s_nvalid;
    __shared__ int s_wcnt[32], s_woff[32];
    __shared__ int s_total;

    int b = blockIdx.x >> 5, c = blockIdx.x & 31;
    int tid = threadIdx.x; // 1024 threads

    const unsigned long long* key = g_skey + ((size_t)b * NCLS + c) * NBOX;
    if (tid == 0) s_nvalid = NBOX;
    __syncthreads();

    unsigned long long k64 = key[tid];
    int n = (int)(k64 & 0xFFFFFFFFu);
    float sc = decode_score((unsigned int)(k64 >> 32));
    bool valid = sc > SCORE_THRF;

    const float4* bp = (const float4*)boxes + (size_t)b * NBOX;
    float4 bx = bp[n];
    float my_area = __fmul_rn(__fsub_rn(bx.z, bx.x), __fsub_rn(bx.w, bx.y));
    sbox[tid] = bx;
    sarea[tid] = my_area;
    skeep[tid] = valid ? 1 : 0;
    if (!valid) atomicMin(&s_nvalid, tid);
    __syncthreads();

    int nvalid = s_nvalid; // valid entries form a prefix of the sorted order

    for (int i = 0; i < nvalid; i++) {
        if (skeep[i]) {
            if (tid > i && skeep[tid]) {
                float4 bi = sbox[i];
                // exact op-order match with the reference (no fma contraction)
                float yy1 = fmaxf(bi.x, bx.x);
                float xx1 = fmaxf(bi.y, bx.y);
                float yy2 = fminf(bi.z, bx.z);
                float xx2 = fminf(bi.w, bx.w);
                float ih = fmaxf(__fsub_rn(yy2, yy1), 0.0f);
                float iw = fmaxf(__fsub_rn(xx2, xx1), 0.0f);
                float inter = __fmul_rn(ih, iw);
                float denom = __fsub_rn(__fadd_rn(sarea[i], my_area), inter);
                float iou = __fdiv_rn(inter, denom);
                if (iou > IOU_THRF) skeep[tid] = 0;
            }
        }
        __syncthreads();
    }

    // compaction (order-preserving, so candidate list stays key-ascending)
    bool kept = (skeep[tid] != 0);
    int lane = tid & 31, wid = tid >> 5;
    unsigned int mask = __ballot_sync(0xffffffffu, kept);
    if (lane == 0) s_wcnt[wid] = __popc(mask);
    __syncthreads();
    if (tid == 0) {
        int acc = 0;
        for (int w = 0; w < 32; w++) { s_woff[w] = acc; acc += s_wcnt[w]; }
        s_total = acc;
    }
    __syncthreads();
    int rank = s_woff[wid] + __popc(mask & ((1u << lane) - 1u));

    unsigned long long* cp = g_cand + ((size_t)b * NCLS + c) * MAXOUT;
    if (kept && rank < MAXOUT) {
        // global key: same score bits, low word = class-major flatten index c*N+pos
        cp[rank] = (k64 & 0xFFFFFFFF00000000ull) | (unsigned int)(c * NBOX + tid);
    }
    int total = s_total;
    if (tid >= total && tid < MAXOUT) cp[tid] = 0xFFFFFFFFFFFFFFFFull; // pad
}

// ---------------------------------------------------------------------------
// Kernel 3: per-batch global top-300 (5 rounds of truncated merge-path merges
// of the 32 already-sorted candidate lists), dedup by original box index,
// output compaction in ascending box-index order, zero padding.
// ---------------------------------------------------------------------------
__global__ void topk_kernel(const float* __restrict__ boxes, float* __restrict__ out) {
    extern __shared__ unsigned long long sm[]; // A: 9600 + B: 4800 keys
    unsigned long long* A = sm;
    unsigned long long* Bb = sm + NCLS * MAXOUT;
    __shared__ int s_first[NBOX];
    __shared__ int s_wcnt[32], s_woff[32];
    __shared__ int s_np;

    int b = blockIdx.x;
    int tid = threadIdx.x; // 1024 threads

    const unsigned long long* cp = g_cand + (size_t)b * NCLS * MAXOUT;
    for (int i = tid; i < NCLS * MAXOUT; i += blockDim.x) A[i] = cp[i];
    for (int i = tid; i < NBOX; i += blockDim.x) s_first[i] = 0x7FFFFFFF;
    __syncthreads();

    unsigned long long* src = A;
    unsigned long long* dst = Bb;
    int nl = NCLS;
    while (nl > 1) {
        int nout = (nl >> 1) * MAXOUT;
        for (int p = tid; p < nout; p += blockDim.x) {
            int m = p / MAXOUT, off = p % MAXOUT;
            const unsigned long long* La = src + (size_t)(2 * m) * MAXOUT;
            const unsigned long long* Lb = src + (size_t)(2 * m + 1) * MAXOUT;
            // merge-path: off-th smallest of La ∪ Lb (keys globally unique)
            int lo = 0, hi = off;
            while (lo < hi) {
                int a = (lo + hi) >> 1;
                if (La[a] < Lb[off - 1 - a]) lo = a + 1; else hi = a;
            }
            int a = lo, bi = off - a; // both <= off <= 299, always in range
            unsigned long long va = La[a], vb = Lb[bi];
            dst[(size_t)m * MAXOUT + off] = va < vb ? va : vb;
        }
        __syncthreads();
        unsigned long long* t = src; src = dst; dst = t;
        nl >>= 1;
    }
    const unsigned long long* T = src; // top-300, key-ascending = score-descending

    // dedup: first (best) top-300 position per original box index
    const unsigned long long* skeyb = g_skey + (size_t)b * NCLS * NBOX;
    if (tid < MAXOUT) {
        unsigned long long k64 = T[tid];
        float sc = decode_score((unsigned int)(k64 >> 32));
        if (sc > SCORE_THRF) { // padding decodes to +0 / -inf -> skipped
            int flat = (int)(k64 & 0xFFFFFFFFu);
            int cc = flat >> 10, pos = flat & 1023;
            int orig = (int)(skeyb[(size_t)cc * NBOX + pos] & 0xFFFFFFFFu);
            atomicMin(&s_first[orig], tid);
        }
    }
    __syncthreads();

    bool present = (s_first[tid] < 0x7FFFFFFF);
    int lane = tid & 31, wid = tid >> 5;
    unsigned int mask = __ballot_sync(0xffffffffu, present);
    if (lane == 0) s_wcnt[wid] = __popc(mask);
    __syncthreads();
    if (tid == 0) {
        int acc = 0;
        for (int w = 0; w < 32; w++) { s_woff[w] = acc; acc += s_wcnt[w]; }
        s_np = acc;
    }
    __syncthreads();
    int row = s_woff[wid] + __popc(mask & ((1u << lane) - 1u));

    float* ob = out;                              // [8,300,4]
    float* os = out + (size_t)BATCH * MAXOUT * 4; // [8,300]
    float* oc = os + (size_t)BATCH * MAXOUT;      // [8,300] (classes as float)

    if (present) {
        int p = s_first[tid];
        unsigned long long k64 = T[p];
        float sc = decode_score((unsigned int)(k64 >> 32));
        int flat = (int)(k64 & 0xFFFFFFFFu);
        int cc = flat >> 10;
        float4 bx = ((const float4*)boxes)[(size_t)b * NBOX + tid]; // original box coords
        ((float4*)ob)[(size_t)b * MAXOUT + row] = bx;
        os[(size_t)b * MAXOUT + row] = sc;
        oc[(size_t)b * MAXOUT + row] = (float)cc;
    }
    int np = s_np;
    if (tid >= np && tid < MAXOUT) {
        ((float4*)ob)[(size_t)b * MAXOUT + tid] = make_float4(0.f, 0.f, 0.f, 0.f);
        os[(size_t)b * MAXOUT + tid] = 0.f;
        oc[(size_t)b * MAXOUT + tid] = 0.f;
    }
}

// ---------------------------------------------------------------------------
extern "C" void kernel_launch(void* const* d_in, const int* in_sizes, int n_in,
                              void* d_out, int out_size) {
    const float* boxes  = (const float*)d_in[0];
    const float* scores = (const float*)d_in[1];
    // defensive: identify by element count (boxes=32768, scores=262144)
    if (n_in >= 2 && in_sizes[0] == BATCH * NBOX * NCLS && in_sizes[1] == BATCH * NBOX * 4) {
        scores = (const float*)d_in[0];
        boxes  = (const float*)d_in[1];
    }
    float* out = (float*)d_out;

    size_t topk_smem = (size_t)(NCLS * MAXOUT + (NCLS / 2) * MAXOUT) * sizeof(unsigned long long); // 115200
    cudaFuncSetAttribute(topk_kernel, cudaFuncAttributeMaxDynamicSharedMemorySize, (int)topk_smem);

    sort_kernel<<<BATCH * NCLS, 256>>>(scores);
    nms_kernel<<<BATCH * NCLS, NBOX>>>(boxes);
    topk_kernel<<<BATCH, NBOX, topk_smem>>>(boxes, out);
}